// round 8
// baseline (speedup 1.0000x reference)
#include <cuda_runtime.h>
#include <cuda_bf16.h>
#include <math.h>
#include <stdint.h>

#define Bsz 1024
#define Tsz 128
#define Fd 1024
#define Zd 256
#define Td 768
#define Hn 8
#define Dh 128

// fp32 scratch
__device__ float g_gb[Bsz * 2 * Fd];     // gamma||beta [1024, 2048]
__device__ float g_h1[Bsz * Fd];
__device__ float g_out[Bsz * Fd];
__device__ float g_q[Bsz * Fd];
__device__ float g_qt[Bsz * Hn * Td];
__device__ float g_u[Bsz * Hn * Td];
__device__ float g_ctx[Bsz * Fd];
__device__ float g_ao[Bsz * Fd];
__device__ float g_bgb[2 * Fd];          // bg||bb

// bf16 hi/lo pre-split weights
__device__ __nv_bfloat16 g_Wgb_h[2 * Fd * Zd], g_Wgb_l[2 * Fd * Zd]; // Wg||Wb
__device__ __nv_bfloat16 g_Wl_h[Fd * Fd],  g_Wl_l[Fd * Fd];
__device__ __nv_bfloat16 g_Wq_h[Fd * Fd],  g_Wq_l[Fd * Fd];
__device__ __nv_bfloat16 g_Wo_h[Fd * Fd],  g_Wo_l[Fd * Fd];
__device__ __nv_bfloat16 g_Wv_h[Fd * Td],  g_Wv_l[Fd * Td];
__device__ __nv_bfloat16 g_WkT_h[Hn * Td * Dh], g_WkT_l[Hn * Td * Dh];

// ---------------------------------------------------------------------------
__device__ __forceinline__ uint32_t smem_u32(const void* p) {
    uint32_t a;
    asm("{ .reg .u64 t; cvta.to.shared.u64 t, %1; cvt.u32.u64 %0, t; }"
        : "=r"(a) : "l"(p));
    return a;
}
__device__ __forceinline__ uint32_t pack_bf2(float lo, float hi) {
    uint32_t r;
    asm("cvt.rn.bf16x2.f32 %0, %1, %2;" : "=r"(r) : "f"(hi), "f"(lo));
    return r;
}
__device__ __forceinline__ void mma_bf16(float* c, uint32_t a0, uint32_t a1,
                                         uint32_t a2, uint32_t a3,
                                         uint32_t b0, uint32_t b1) {
    asm volatile(
        "mma.sync.aligned.m16n8k16.row.col.f32.bf16.bf16.f32 "
        "{%0,%1,%2,%3}, {%4,%5,%6,%7}, {%8,%9}, {%0,%1,%2,%3};\n"
        : "+f"(c[0]), "+f"(c[1]), "+f"(c[2]), "+f"(c[3])
        : "r"(a0), "r"(a1), "r"(a2), "r"(a3), "r"(b0), "r"(b1));
}
#define LDSM4(r0, r1, r2, r3, addr) \
    asm volatile("ldmatrix.sync.aligned.m8n8.x4.shared.b16 {%0,%1,%2,%3}, [%4];" \
                 : "=r"(r0), "=r"(r1), "=r"(r2), "=r"(r3) : "r"(addr))

// packed fp32x2 (B300 FFMA2)
#define PACK2(d, a, b) do { unsigned _lo = __float_as_uint(a), _hi = __float_as_uint(b); \
    asm("mov.b64 %0, {%1,%2};" : "=l"(d) : "r"(_lo), "r"(_hi)); } while (0)
#define UNPACK2(a, b, s) do { unsigned _lo, _hi; \
    asm("mov.b64 {%0,%1}, %2;" : "=r"(_lo), "=r"(_hi) : "l"(s)); \
    a = __uint_as_float(_lo); b = __uint_as_float(_hi); } while (0)
#define FMA2(d, a, b) \
    asm("fma.rn.f32x2 %0, %1, %2, %0;" : "+l"(d) : "l"(a), "l"(b))
#define MUL2(d, a) \
    asm("mul.rn.f32x2 %0, %0, %1;" : "+l"(d) : "l"(a))

// ===========================================================================
// mma.sync NT GEMM (unchanged from round 6): BM=128 BN=32 BK=32
// ===========================================================================
#define PK 40                 // smem pitch (bf16)
#define AL_OFF 10240
#define BH_OFF 20480
#define BL_OFF 23040
#define STG3 25600            // stage stride bytes
#define GEMM_SMEM (2 * STG3)

__global__ __launch_bounds__(256) void bgemm3(
    const float* __restrict__ A, int lda, int a_bs,
    const __nv_bfloat16* __restrict__ Bh_g, const __nv_bfloat16* __restrict__ Bl_g,
    int ldb, int b_bs,
    const float* __restrict__ bias, int bias_bs,
    float* __restrict__ C, int ldc, int c_bs,
    int K, float alpha)
{
    extern __shared__ char smg[];
    const uint32_t sb = smem_u32(smg);
    const int tid = threadIdx.x, lane = tid & 31, warp = tid >> 5;
    const int wm = warp & 3, wn = warp >> 2;
    const int m0 = blockIdx.y * 128, n0 = blockIdx.x * 32, z = blockIdx.z;

    const float* Ap = A + (size_t)z * a_bs + (size_t)(m0 + (tid >> 1)) * lda
                        + (tid & 1) * 16;
    const __nv_bfloat16* Bph = Bh_g + (size_t)z * b_bs
                        + (size_t)(n0 + (tid >> 3)) * ldb + (tid & 7) * 4;
    const __nv_bfloat16* Bpl = Bl_g + (size_t)z * b_bs
                        + (size_t)(n0 + (tid >> 3)) * ldb + (tid & 7) * 4;

    const int a_sts = ((tid >> 1) * PK + (tid & 1) * 16) * 2;
    const int b_sts = ((tid >> 3) * PK + (tid & 7) * 4) * 2;
    const uint32_t a_lds = ((wm * 32 + (lane & 15)) * PK + (lane >> 4) * 8) * 2;
    const uint32_t b_lds = ((wn * 16 + (lane & 15)) * PK + (lane >> 4) * 8) * 2;

    float4 av[4];
    uint2 bvh, bvl;

    auto ldg = [&](int k0) {
        av[0] = *(const float4*)(Ap + k0);
        av[1] = *(const float4*)(Ap + k0 + 4);
        av[2] = *(const float4*)(Ap + k0 + 8);
        av[3] = *(const float4*)(Ap + k0 + 12);
        bvh = *(const uint2*)(Bph + k0);
        bvl = *(const uint2*)(Bpl + k0);
    };
    auto sts = [&](int s) {
        char* base = smg + s * STG3;
        const float* af = (const float*)av;
        uint32_t hp[8], lp[8];
#pragma unroll
        for (int j = 0; j < 8; j++) {
            float x0 = af[2 * j], x1 = af[2 * j + 1];
            __nv_bfloat16 h0 = __float2bfloat16(x0), h1 = __float2bfloat16(x1);
            hp[j] = ((uint32_t)__bfloat16_as_ushort(h1) << 16) |
                    __bfloat16_as_ushort(h0);
            lp[j] = pack_bf2(x0 - __bfloat162float(h0), x1 - __bfloat162float(h1));
        }
        *(uint4*)(base + a_sts)           = make_uint4(hp[0], hp[1], hp[2], hp[3]);
        *(uint4*)(base + a_sts + 16)      = make_uint4(hp[4], hp[5], hp[6], hp[7]);
        *(uint4*)(base + AL_OFF + a_sts)      = make_uint4(lp[0], lp[1], lp[2], lp[3]);
        *(uint4*)(base + AL_OFF + a_sts + 16) = make_uint4(lp[4], lp[5], lp[6], lp[7]);
        *(uint2*)(base + BH_OFF + b_sts) = bvh;
        *(uint2*)(base + BL_OFF + b_sts) = bvl;
    };

    float acc[2][2][4] = {};
    const int nch = K >> 5;

    ldg(0);
    sts(0);
    __syncthreads();

    for (int c = 0; c < nch; ++c) {
        const int buf = c & 1;
        if (c + 1 < nch) ldg((c + 1) << 5);

        const uint32_t ab = sb + buf * STG3 + a_lds;
        const uint32_t bb = sb + buf * STG3 + BH_OFF + b_lds;
#pragma unroll
        for (int kk = 0; kk < 2; kk++) {
            const uint32_t ko = kk * 32;
            uint32_t ah[2][4], al[2][4], bh[4], bl[4];
#pragma unroll
            for (int mr = 0; mr < 2; mr++) {
                LDSM4(ah[mr][0], ah[mr][1], ah[mr][2], ah[mr][3],
                      ab + mr * 1280 + ko);
                LDSM4(al[mr][0], al[mr][1], al[mr][2], al[mr][3],
                      ab + AL_OFF + mr * 1280 + ko);
            }
            LDSM4(bh[0], bh[1], bh[2], bh[3], bb + ko);
            LDSM4(bl[0], bl[1], bl[2], bl[3], bb + 2560 + ko);
#pragma unroll
            for (int mr = 0; mr < 2; mr++) {
                float* c0 = acc[mr][0];
                float* c1 = acc[mr][1];
                mma_bf16(c0, ah[mr][0], ah[mr][1], ah[mr][2], ah[mr][3], bh[0], bh[2]);
                mma_bf16(c0, ah[mr][0], ah[mr][1], ah[mr][2], ah[mr][3], bl[0], bl[2]);
                mma_bf16(c0, al[mr][0], al[mr][1], al[mr][2], al[mr][3], bh[0], bh[2]);
                mma_bf16(c1, ah[mr][0], ah[mr][1], ah[mr][2], ah[mr][3], bh[1], bh[3]);
                mma_bf16(c1, ah[mr][0], ah[mr][1], ah[mr][2], ah[mr][3], bl[1], bl[3]);
                mma_bf16(c1, al[mr][0], al[mr][1], al[mr][2], al[mr][3], bh[1], bh[3]);
            }
        }
        if (c + 1 < nch) sts((c + 1) & 1);
        __syncthreads();
    }

    const int gid = lane >> 2, tig = lane & 3;
#pragma unroll
    for (int mr = 0; mr < 2; mr++) {
#pragma unroll
        for (int nc = 0; nc < 2; nc++) {
            int m = m0 + wm * 32 + mr * 16 + gid;
            int n = n0 + wn * 16 + nc * 8 + tig * 2;
            float b0 = 0.f, b1 = 0.f;
            if (bias) {
                b0 = bias[(size_t)z * bias_bs + n];
                b1 = bias[(size_t)z * bias_bs + n + 1];
            }
            float2 o0, o1;
            o0.x = fmaf(acc[mr][nc][0], alpha, b0);
            o0.y = fmaf(acc[mr][nc][1], alpha, b1);
            o1.x = fmaf(acc[mr][nc][2], alpha, b0);
            o1.y = fmaf(acc[mr][nc][3], alpha, b1);
            *(float2*)&C[(size_t)z * c_bs + (size_t)m * ldc + n] = o0;
            *(float2*)&C[(size_t)z * c_bs + (size_t)(m + 8) * ldc + n] = o1;
        }
    }
}

// ---------------------------------------------------------------------------
// Merged prep (unchanged)
// ---------------------------------------------------------------------------
__device__ __forceinline__ void split4(const float* __restrict__ s, int i,
                                       __nv_bfloat16* __restrict__ h,
                                       __nv_bfloat16* __restrict__ l)
{
    float4 v = *(const float4*)(s);
    __nv_bfloat16 h0 = __float2bfloat16(v.x), h1 = __float2bfloat16(v.y);
    __nv_bfloat16 h2 = __float2bfloat16(v.z), h3 = __float2bfloat16(v.w);
    uint2 hw, lw;
    hw.x = ((uint32_t)__bfloat16_as_ushort(h1) << 16) | __bfloat16_as_ushort(h0);
    hw.y = ((uint32_t)__bfloat16_as_ushort(h3) << 16) | __bfloat16_as_ushort(h2);
    lw.x = pack_bf2(v.x - __bfloat162float(h0), v.y - __bfloat162float(h1));
    lw.y = pack_bf2(v.z - __bfloat162float(h2), v.w - __bfloat162float(h3));
    *(uint2*)(h + i) = hw;
    *(uint2*)(l + i) = lw;
}

__global__ __launch_bounds__(256) void prep_kernel(
    const float* __restrict__ Wg, const float* __restrict__ Wb,
    const float* __restrict__ Wl, const float* __restrict__ Wq,
    const float* __restrict__ Wo, const float* __restrict__ Wv,
    const float* __restrict__ bg, const float* __restrict__ bb,
    __nv_bfloat16* __restrict__ wgb_h, __nv_bfloat16* __restrict__ wgb_l,
    __nv_bfloat16* __restrict__ wl_h, __nv_bfloat16* __restrict__ wl_l,
    __nv_bfloat16* __restrict__ wq_h, __nv_bfloat16* __restrict__ wq_l,
    __nv_bfloat16* __restrict__ wo_h, __nv_bfloat16* __restrict__ wo_l,
    __nv_bfloat16* __restrict__ wv_h, __nv_bfloat16* __restrict__ wv_l,
    float* __restrict__ bgb)
{
    const int blk = blockIdx.x, t4 = threadIdx.x * 4;
    if (blk < 512) {
        int i = blk * 1024 + t4;
        const float* s = (i < Fd * Zd) ? (Wg + i) : (Wb + (i - Fd * Zd));
        split4(s, i, wgb_h, wgb_l);
    } else if (blk < 1536) {
        int i = (blk - 512) * 1024 + t4;
        split4(Wl + i, i, wl_h, wl_l);
    } else if (blk < 2560) {
        int i = (blk - 1536) * 1024 + t4;
        split4(Wq + i, i, wq_h, wq_l);
    } else if (blk < 3584) {
        int i = (blk - 2560) * 1024 + t4;
        split4(Wo + i, i, wo_h, wo_l);
    } else if (blk < 4352) {
        int i = (blk - 3584) * 1024 + t4;
        split4(Wv + i, i, wv_h, wv_l);
    } else {
        int i = (blk - 4352) * 1024 + t4;
        const float* s = (i < Fd) ? (bg + i) : (bb + (i - Fd));
        *(float4*)(bgb + i) = *(const float4*)s;
    }
}

__global__ __launch_bounds__(256) void splitT_wk(
    const float* __restrict__ w, __nv_bfloat16* __restrict__ h,
    __nv_bfloat16* __restrict__ l)
{
    int idx = blockIdx.x * 256 + threadIdx.x;
    int d = idx & 127;
    int c = (idx >> 7) % Td;
    int hh = idx / (128 * Td);
    float v = w[((size_t)hh * 128 + d) * Td + c];
    __nv_bfloat16 hi = __float2bfloat16(v);
    h[idx] = hi;
    l[idx] = __float2bfloat16(v - __bfloat162float(hi));
}

// ---------------------------------------------------------------------------
// LayerNorm + FiLM (unchanged)
// ---------------------------------------------------------------------------
__global__ __launch_bounds__(256) void ln_film_kernel(
    const float* __restrict__ h1, const float* __restrict__ g,
    const float* __restrict__ bb, const float* __restrict__ gb,
    float* __restrict__ out)
{
    int r = blockIdx.x, tid = threadIdx.x;
    __shared__ float red1[8], red2[8], mv[2];
    const float* row = h1 + (size_t)r * Fd;
    float v[4], s = 0.f, s2 = 0.f;
#pragma unroll
    for (int i = 0; i < 4; i++) {
        v[i] = row[tid + i * 256];
        s += v[i]; s2 += v[i] * v[i];
    }
#pragma unroll
    for (int o = 16; o; o >>= 1) {
        s += __shfl_xor_sync(~0u, s, o);
        s2 += __shfl_xor_sync(~0u, s2, o);
    }
    if ((tid & 31) == 0) { red1[tid >> 5] = s; red2[tid >> 5] = s2; }
    __syncthreads();
    if (tid == 0) {
        float a = 0.f, b2 = 0.f;
        for (int w = 0; w < 8; w++) { a += red1[w]; b2 += red2[w]; }
        mv[0] = a * (1.f / Fd); mv[1] = b2 * (1.f / Fd);
    }
    __syncthreads();
    float mu = mv[0], var = mv[1] - mu * mu;
    float rstd = rsqrtf(var + 1e-5f);
#pragma unroll
    for (int i = 0; i < 4; i++) {
        int f = tid + i * 256;
        float y = (v[i] - mu) * rstd * g[f] + bb[f];
        float gamma = gb[(size_t)r * 2048 + f];
        float beta  = gb[(size_t)r * 2048 + 1024 + f];
        out[(size_t)r * Fd + f] = y * (1.f + gamma) + beta;
    }
}

__global__ __launch_bounds__(256) void ln_add_gelu_kernel(
    const float* __restrict__ ao, const float* __restrict__ g,
    const float* __restrict__ bb, const float* __restrict__ res,
    float* __restrict__ y)
{
    int r = blockIdx.x, tid = threadIdx.x;
    __shared__ float red1[8], red2[8], mv[2];
    const float* row = ao + (size_t)r * Fd;
    float v[4], s = 0.f, s2 = 0.f;
#pragma unroll
    for (int i = 0; i < 4; i++) {
        v[i] = row[tid + i * 256];
        s += v[i]; s2 += v[i] * v[i];
    }
#pragma unroll
    for (int o = 16; o; o >>= 1) {
        s += __shfl_xor_sync(~0u, s, o);
        s2 += __shfl_xor_sync(~0u, s2, o);
    }
    if ((tid & 31) == 0) { red1[tid >> 5] = s; red2[tid >> 5] = s2; }
    __syncthreads();
    if (tid == 0) {
        float a = 0.f, b2 = 0.f;
        for (int w = 0; w < 8; w++) { a += red1[w]; b2 += red2[w]; }
        mv[0] = a * (1.f / Fd); mv[1] = b2 * (1.f / Fd);
    }
    __syncthreads();
    float mu = mv[0], var = mv[1] - mu * mu;
    float rstd = rsqrtf(var + 1e-5f);
#pragma unroll
    for (int i = 0; i < 4; i++) {
        int f = tid + i * 256;
        float t = res[(size_t)r * Fd + f] + ((v[i] - mu) * rstd * g[f] + bb[f]);
        y[(size_t)r * Fd + f] = t * normcdff(t);
    }
}

// ---------------------------------------------------------------------------
// Fused attention v7: score pass via mma.sync (16t x 8h x 768c GEMM,
// k-split across 8 warps, q-fragments chunk-invariant in registers),
// online softmax on warp 0 (shuffle-parallel over t), u-pass FMA2 c-split.
// Text loaded once, split to bf16 hi/lo tiles (Markidis 3-pass numerics).
// ---------------------------------------------------------------------------
#define TPITCH 776                         // bf16 pitch per t-row (conflict-free LDSM)
#define TILE_BYTES (16 * TPITCH * 2)       // 24832
#define PS_OFF (2 * TILE_BYTES)            // partial scores [8][16][8] f32
#define PSM_OFF (PS_OFF + 4096)            // p [16][8] f32
#define RS_OFF (PSM_OFF + 512)             // rs [8]
#define IL_OFF (RS_OFF + 32)               // 1/l [8]
#define ATTN_SMEM (IL_OFF + 32)

__global__ __launch_bounds__(256) void attn_kernel(
    const float* __restrict__ text, const int* __restrict__ att,
    const float* __restrict__ qt, float* __restrict__ u)
{
    extern __shared__ char sma[];
    __nv_bfloat16* th = (__nv_bfloat16*)sma;
    __nv_bfloat16* tl = th + 16 * TPITCH;
    float* ps    = (float*)(sma + PS_OFF);
    float* p_sm  = (float*)(sma + PSM_OFF);
    float* rs_sm = (float*)(sma + RS_OFF);
    float* il_sm = (float*)(sma + IL_OFF);
    __shared__ int s_att[128];

    const int b = blockIdx.x, tid = threadIdx.x;
    const int w = tid >> 5, lane = tid & 31;
    const int cw = w * 96;

    // --- q-fragments (B of m16n8k16), chunk-invariant, built from gmem ---
    // frag layout: lane t: n(head) = t>>2; reg r: k_local = (t&3)*2 + r*8
    uint32_t qh[6][2], ql[6][2];
    {
        const float* qb = qt + (size_t)b * (Hn * Td) + (lane >> 2) * Td;
#pragma unroll
        for (int s = 0; s < 6; s++)
#pragma unroll
            for (int r = 0; r < 2; r++) {
                int c0 = cw + s * 16 + (lane & 3) * 2 + r * 8;
                float2 v = *(const float2*)(qb + c0);
                __nv_bfloat16 h0 = __float2bfloat16(v.x);
                __nv_bfloat16 h1 = __float2bfloat16(v.y);
                qh[s][r] = ((uint32_t)__bfloat16_as_ushort(h1) << 16) |
                           __bfloat16_as_ushort(h0);
                ql[s][r] = pack_bf2(v.x - __bfloat162float(h0),
                                    v.y - __bfloat162float(h1));
            }
    }

    unsigned long long u2[4][3] = {};   // u accumulators, packed head pairs
    float m_run4[4], l_run4[4];         // softmax state (warp 0 only)
#pragma unroll
    for (int q = 0; q < 4; q++) { m_run4[q] = -INFINITY; l_run4[q] = 0.f; }

    for (int i = tid; i < 128; i += 256) s_att[i] = att[b * 128 + i];

    const float* tb = text + (size_t)b * Tsz * Td;
    const uint32_t th_base = smem_u32(th);
    const uint32_t a_lds = th_base +
        ((lane & 15) * TPITCH + cw + (lane >> 4) * 8) * 2;

    for (int tc = 0; tc < 8; tc++) {
        __syncthreads();
        // load text chunk, split to bf16 hi/lo tiles
        for (int i = tid; i < 3072; i += 256) {
            float4 v = *(const float4*)(tb + tc * 12288 + i * 4);
            int t = (i * 4) / 768, c = (i * 4) % 768;
            int addr = t * TPITCH + c;
            __nv_bfloat16 h0 = __float2bfloat16(v.x), h1 = __float2bfloat16(v.y);
            __nv_bfloat16 h2 = __float2bfloat16(v.z), h3 = __float2bfloat16(v.w);
            uint2 hw, lw;
            hw.x = ((uint32_t)__bfloat16_as_ushort(h1) << 16) |
                   __bfloat16_as_ushort(h0);
            hw.y = ((uint32_t)__bfloat16_as_ushort(h3) << 16) |
                   __bfloat16_as_ushort(h2);
            lw.x = pack_bf2(v.x - __bfloat162float(h0), v.y - __bfloat162float(h1));
            lw.y = pack_bf2(v.z - __bfloat162float(h2), v.w - __bfloat162float(h3));
            *(uint2*)&th[addr] = hw;
            *(uint2*)&tl[addr] = lw;
        }
        __syncthreads();

        // --- score mma: this warp's 96-channel k-slice ---
        float acc[4] = {0.f, 0.f, 0.f, 0.f};
#pragma unroll
        for (int s = 0; s < 6; s++) {
            uint32_t Ah[4], Al[4];
            LDSM4(Ah[0], Ah[1], Ah[2], Ah[3], a_lds + s * 32);
            LDSM4(Al[0], Al[1], Al[2], Al[3], a_lds + TILE_BYTES + s * 32);
            mma_bf16(acc, Ah[0], Ah[1], Ah[2], Ah[3], qh[s][0], qh[s][1]);
            mma_bf16(acc, Ah[0], Ah[1], Ah[2], Ah[3], ql[s][0], ql[s][1]);
            mma_bf16(acc, Al[0], Al[1], Al[2], Al[3], qh[s][0], qh[s][1]);
        }
        // partial scores: acc rows t = (lane>>2), (lane>>2)+8; cols h = (lane&3)*2,+1
        *(float2*)&ps[w * 128 + (lane >> 2) * 8 + (lane & 3) * 2] =
            make_float2(acc[0], acc[1]);
        *(float2*)&ps[w * 128 + ((lane >> 2) + 8) * 8 + (lane & 3) * 2] =
            make_float2(acc[2], acc[3]);
        __syncthreads();

        // --- online softmax on warp 0: lane = (t = lane>>1, hq = (lane&1)*4) ---
        if (w == 0) {
            const int t = lane >> 1, hq = (lane & 1) * 4;
            float s4[4] = {0.f, 0.f, 0.f, 0.f};
#pragma unroll
            for (int ww = 0; ww < 8; ww++) {
                float4 pv = *(float4*)&ps[ww * 128 + t * 8 + hq];
                s4[0] += pv.x; s4[1] += pv.y; s4[2] += pv.z; s4[3] += pv.w;
            }
            const bool ok = s_att[tc * 16 + t] != 0;
            float p4[4], rs4[4];
#pragma unroll
            for (int q = 0; q < 4; q++) {
                float sc = ok ? s4[q] : -INFINITY;
                float mx = sc;
#pragma unroll
                for (int off = 2; off < 32; off <<= 1)
                    mx = fmaxf(mx, __shfl_xor_sync(~0u, mx, off));
                mx = fmaxf(mx, m_run4[q]);
                float p = (sc == -INFINITY) ? 0.f : expf(sc - mx);
                float rs = (mx == -INFINITY) ? 1.f : expf(m_run4[q] - mx);
                float psum = p;
#pragma unroll
                for (int off = 2; off < 32; off <<= 1)
                    psum += __shfl_xor_sync(~0u, psum, off);
                l_run4[q] = l_run4[q] * rs + psum;
                m_run4[q] = mx;
                p4[q] = p; rs4[q] = rs;
            }
            *(float4*)&p_sm[t * 8 + hq] = make_float4(p4[0], p4[1], p4[2], p4[3]);
            if (t == 0)
                *(float4*)&rs_sm[hq] = make_float4(rs4[0], rs4[1], rs4[2], rs4[3]);
        }
        __syncthreads();

        // --- u pass: c-split, FMA2 over head pairs ---
        unsigned long long rs2[4];
#pragma unroll
        for (int hp = 0; hp < 4; hp++) {
            float2 rv = *(const float2*)&rs_sm[2 * hp];
            PACK2(rs2[hp], rv.x, rv.y);
        }
#pragma unroll
        for (int hp = 0; hp < 4; hp++)
#pragma unroll
            for (int j = 0; j < 3; j++) MUL2(u2[hp][j], rs2[hp]);

#pragma unroll
        for (int t = 0; t < 16; t++) {
            unsigned long long xx[3];
#pragma unroll
            for (int j = 0; j < 3; j++) {
                int o = t * TPITCH + cw + lane + 32 * j;
                float x = __bfloat162float(th[o]) + __bfloat162float(tl[o]);
                PACK2(xx[j], x, x);
            }
            unsigned long long p2[4];
#pragma unroll
            for (int hp = 0; hp < 4; hp++) {
                float2 pv = *(const float2*)&p_sm[t * 8 + 2 * hp];
                PACK2(p2[hp], pv.x, pv.y);
            }
#pragma unroll
            for (int hp = 0; hp < 4; hp++) {
                FMA2(u2[hp][0], p2[hp], xx[0]);
                FMA2(u2[hp][1], p2[hp], xx[1]);
                FMA2(u2[hp][2], p2[hp], xx[2]);
            }
        }
    }

    if (w == 0 && (lane >> 1) == 0) {
        const int hq = (lane & 1) * 4;
#pragma unroll
        for (int q = 0; q < 4; q++) il_sm[hq + q] = 1.f / l_run4[q];
    }
    __syncthreads();

    float* ub = u + (size_t)b * (Hn * Td);
#pragma unroll
    for (int hp = 0; hp < 4; hp++) {
        float il0 = il_sm[2 * hp], il1 = il_sm[2 * hp + 1];
#pragma unroll
        for (int j = 0; j < 3; j++) {
            float lo, hi;
            UNPACK2(lo, hi, u2[hp][j]);
            ub[(2 * hp) * Td + cw + lane + 32 * j]     = lo * il0;
            ub[(2 * hp + 1) * Td + cw + lane + 32 * j] = hi * il1;
        }
    }
}

// ---------------------------------------------------------------------------
extern "C" void kernel_launch(void* const* d_in, const int* in_sizes, int n_in,
                              void* d_out, int out_size)
{
    const float* x    = (const float*)d_in[0];
    const float* z    = (const float*)d_in[1];
    const float* text = (const float*)d_in[2];
    const int*   att  = (const int*)d_in[3];
    const float* Wg = (const float*)d_in[4];  const float* bg = (const float*)d_in[5];
    const float* Wb = (const float*)d_in[6];  const float* bb = (const float*)d_in[7];
    const float* Wl = (const float*)d_in[8];  const float* bl = (const float*)d_in[9];
    const float* g1 = (const float*)d_in[10]; const float* b1 = (const float*)d_in[11];
    const float* Wq = (const float*)d_in[12]; const float* bq = (const float*)d_in[13];
    const float* Wk = (const float*)d_in[14]; /* bk softmax-invariant: dropped */
    const float* Wv = (const float*)d_in[16]; const float* bv = (const float*)d_in[17];
    const float* Wo = (const float*)d_in[18]; const float* bo = (const float*)d_in[19];
    const float* g2 = (const float*)d_in[20]; const float* b2 = (const float*)d_in[21];
    float* y = (float*)d_out;

    float *p_gb, *p_h1, *p_out, *p_q, *p_qt, *p_u, *p_ctx, *p_ao, *p_bgb;
    cudaGetSymbolAddress((void**)&p_gb,  g_gb);
    cudaGetSymbolAddress((void**)&p_h1,  g_h1);
    cudaGetSymbolAddress((void**)&p_out, g_out);
    cudaGetSymbolAddress((void**)&p_q,   g_q);
    cudaGetSymbolAddress((void**)&p_qt,  g_qt);
    cudaGetSymbolAddress((void**)&p_u,   g_u);
    cudaGetSymbolAddress((void**)&p_ctx, g_ctx);
    cudaGetSymbolAddress((void**)&p_ao,  g_ao);
    cudaGetSymbolAddress((void**)&p_bgb, g_bgb);

    __nv_bfloat16 *wgb_h, *wgb_l, *wl_h, *wl_l, *wq_h, *wq_l;
    __nv_bfloat16 *wo_h, *wo_l, *wv_h, *wv_l, *wk_h, *wk_l;
    cudaGetSymbolAddress((void**)&wgb_h, g_Wgb_h);
    cudaGetSymbolAddress((void**)&wgb_l, g_Wgb_l);
    cudaGetSymbolAddress((void**)&wl_h, g_Wl_h); cudaGetSymbolAddress((void**)&wl_l, g_Wl_l);
    cudaGetSymbolAddress((void**)&wq_h, g_Wq_h); cudaGetSymbolAddress((void**)&wq_l, g_Wq_l);
    cudaGetSymbolAddress((void**)&wo_h, g_Wo_h); cudaGetSymbolAddress((void**)&wo_l, g_Wo_l);
    cudaGetSymbolAddress((void**)&wv_h, g_Wv_h); cudaGetSymbolAddress((void**)&wv_l, g_Wv_l);
    cudaGetSymbolAddress((void**)&wk_h, g_WkT_h); cudaGetSymbolAddress((void**)&wk_l, g_WkT_l);

    cudaFuncSetAttribute(bgemm3, cudaFuncAttributeMaxDynamicSharedMemorySize,
                         GEMM_SMEM);
    cudaFuncSetAttribute(attn_kernel, cudaFuncAttributeMaxDynamicSharedMemorySize,
                         ATTN_SMEM);

    dim3 blk(256);

    prep_kernel<<<4354, blk>>>(Wg, Wb, Wl, Wq, Wo, Wv, bg, bb,
                               wgb_h, wgb_l, wl_h, wl_l, wq_h, wq_l,
                               wo_h, wo_l, wv_h, wv_l, p_bgb);
    splitT_wk<<<(Hn * Td * Dh) / 256, blk>>>(Wk, wk_h, wk_l);

    // gamma||beta = z @ [Wg;Wb]^T + [bg;bb]
    bgemm3<<<dim3(64, 8, 1), blk, GEMM_SMEM>>>(z, Zd, 0, wgb_h, wgb_l, Zd, 0,
                                               p_bgb, 0, p_gb, 2 * Fd, 0, Zd, 1.f);
    // h1 = x @ Wl^T + bl
    bgemm3<<<dim3(32, 8, 1), blk, GEMM_SMEM>>>(x, Fd, 0, wl_h, wl_l, Fd, 0, bl, 0,
                                               p_h1, Fd, 0, Fd, 1.f);
    ln_film_kernel<<<1024, blk>>>(p_h1, g1, b1, p_gb, p_out);
    // q = out @ Wq^T + bq
    bgemm3<<<dim3(32, 8, 1), blk, GEMM_SMEM>>>(p_out, Fd, 0, wq_h, wq_l, Fd, 0,
                                               bq, 0, p_q, Fd, 0, Fd, 1.f);
    // qt = (1/sqrt(d)) q_h @ WkT_h  (batched over heads)
    bgemm3<<<dim3(24, 8, 8), blk, GEMM_SMEM>>>(p_q, Fd, Dh, wk_h, wk_l, Dh,
                                               Td * Dh, nullptr, 0,
                                               p_qt, Hn * Td, Td, Dh,
                                               0.08838834764831845f);
    // fused attention (mma score pass)
    attn_kernel<<<1024, blk, ATTN_SMEM>>>(text, att, p_qt, p_u);
    // ctx = u @ Wv^T + bv
    bgemm3<<<dim3(4, 8, 8), blk, GEMM_SMEM>>>(p_u, Hn * Td, Td, wv_h, wv_l, Td,
                                              Dh * Td, bv, Dh,
                                              p_ctx, Fd, Dh, Td, 1.f);
    // attn_out = ctx @ Wo^T + bo
    bgemm3<<<dim3(32, 8, 1), blk, GEMM_SMEM>>>(p_ctx, Fd, 0, wo_h, wo_l, Fd, 0,
                                               bo, 0, p_ao, Fd, 0, Fd, 1.f);
    ln_add_gelu_kernel<<<1024, blk>>>(p_ao, g2, b2, p_out, y);
}

// round 9
// speedup vs baseline: 1.0079x; 1.0079x over previous
#include <cuda_runtime.h>
#include <cuda_bf16.h>
#include <math.h>
#include <stdint.h>

#define Bsz 1024
#define Tsz 128
#define Fd 1024
#define Zd 256
#define Td 768
#define Hn 8
#define Dh 128

// fp32 scratch
__device__ float g_gb[Bsz * 2 * Fd];     // gamma||beta [1024, 2048]
__device__ float g_h1[Bsz * Fd];
__device__ float g_out[Bsz * Fd];
__device__ float g_q[Bsz * Fd];
__device__ float g_qt[Bsz * Hn * Td];
__device__ float g_u[Bsz * Hn * Td];
__device__ float g_ctx[Bsz * Fd];
__device__ float g_ao[Bsz * Fd];
__device__ float g_bgb[2 * Fd];          // bg||bb

// bf16 hi/lo pre-split weights
__device__ __nv_bfloat16 g_Wgb_h[2 * Fd * Zd], g_Wgb_l[2 * Fd * Zd]; // Wg||Wb
__device__ __nv_bfloat16 g_Wl_h[Fd * Fd],  g_Wl_l[Fd * Fd];
__device__ __nv_bfloat16 g_Wq_h[Fd * Fd],  g_Wq_l[Fd * Fd];
__device__ __nv_bfloat16 g_Wo_h[Fd * Fd],  g_Wo_l[Fd * Fd];
__device__ __nv_bfloat16 g_Wv_h[Fd * Td],  g_Wv_l[Fd * Td];
__device__ __nv_bfloat16 g_WkT_h[Hn * Td * Dh], g_WkT_l[Hn * Td * Dh];

// ---------------------------------------------------------------------------
__device__ __forceinline__ uint32_t smem_u32(const void* p) {
    uint32_t a;
    asm("{ .reg .u64 t; cvta.to.shared.u64 t, %1; cvt.u32.u64 %0, t; }"
        : "=r"(a) : "l"(p));
    return a;
}
__device__ __forceinline__ uint32_t pack_bf2(float lo, float hi) {
    uint32_t r;
    asm("cvt.rn.bf16x2.f32 %0, %1, %2;" : "=r"(r) : "f"(hi), "f"(lo));
    return r;
}
__device__ __forceinline__ void mma_bf16(float* c, uint32_t a0, uint32_t a1,
                                         uint32_t a2, uint32_t a3,
                                         uint32_t b0, uint32_t b1) {
    asm volatile(
        "mma.sync.aligned.m16n8k16.row.col.f32.bf16.bf16.f32 "
        "{%0,%1,%2,%3}, {%4,%5,%6,%7}, {%8,%9}, {%0,%1,%2,%3};\n"
        : "+f"(c[0]), "+f"(c[1]), "+f"(c[2]), "+f"(c[3])
        : "r"(a0), "r"(a1), "r"(a2), "r"(a3), "r"(b0), "r"(b1));
}
#define LDSM4(r0, r1, r2, r3, addr) \
    asm volatile("ldmatrix.sync.aligned.m8n8.x4.shared.b16 {%0,%1,%2,%3}, [%4];" \
                 : "=r"(r0), "=r"(r1), "=r"(r2), "=r"(r3) : "r"(addr))

// packed fp32x2 (B300 FFMA2)
#define PACK2(d, a, b) do { unsigned _lo = __float_as_uint(a), _hi = __float_as_uint(b); \
    asm("mov.b64 %0, {%1,%2};" : "=l"(d) : "r"(_lo), "r"(_hi)); } while (0)
#define UNPACK2(a, b, s) do { unsigned _lo, _hi; \
    asm("mov.b64 {%0,%1}, %2;" : "=r"(_lo), "=r"(_hi) : "l"(s)); \
    a = __uint_as_float(_lo); b = __uint_as_float(_hi); } while (0)
#define FMA2(d, a, b) \
    asm("fma.rn.f32x2 %0, %1, %2, %0;" : "+l"(d) : "l"(a), "l"(b))
#define MUL2(d, a) \
    asm("mul.rn.f32x2 %0, %0, %1;" : "+l"(d) : "l"(a))

// ===========================================================================
// mma.sync NT GEMM (unchanged from round 6): BM=128 BN=32 BK=32
// ===========================================================================
#define PK 40                 // smem pitch (bf16)
#define AL_OFF 10240
#define BH_OFF 20480
#define BL_OFF 23040
#define STG3 25600            // stage stride bytes
#define GEMM_SMEM (2 * STG3)

__global__ __launch_bounds__(256) void bgemm3(
    const float* __restrict__ A, int lda, int a_bs,
    const __nv_bfloat16* __restrict__ Bh_g, const __nv_bfloat16* __restrict__ Bl_g,
    int ldb, int b_bs,
    const float* __restrict__ bias, int bias_bs,
    float* __restrict__ C, int ldc, int c_bs,
    int K, float alpha)
{
    extern __shared__ char smg[];
    const uint32_t sb = smem_u32(smg);
    const int tid = threadIdx.x, lane = tid & 31, warp = tid >> 5;
    const int wm = warp & 3, wn = warp >> 2;
    const int m0 = blockIdx.y * 128, n0 = blockIdx.x * 32, z = blockIdx.z;

    const float* Ap = A + (size_t)z * a_bs + (size_t)(m0 + (tid >> 1)) * lda
                        + (tid & 1) * 16;
    const __nv_bfloat16* Bph = Bh_g + (size_t)z * b_bs
                        + (size_t)(n0 + (tid >> 3)) * ldb + (tid & 7) * 4;
    const __nv_bfloat16* Bpl = Bl_g + (size_t)z * b_bs
                        + (size_t)(n0 + (tid >> 3)) * ldb + (tid & 7) * 4;

    const int a_sts = ((tid >> 1) * PK + (tid & 1) * 16) * 2;
    const int b_sts = ((tid >> 3) * PK + (tid & 7) * 4) * 2;
    const uint32_t a_lds = ((wm * 32 + (lane & 15)) * PK + (lane >> 4) * 8) * 2;
    const uint32_t b_lds = ((wn * 16 + (lane & 15)) * PK + (lane >> 4) * 8) * 2;

    float4 av[4];
    uint2 bvh, bvl;

    auto ldg = [&](int k0) {
        av[0] = *(const float4*)(Ap + k0);
        av[1] = *(const float4*)(Ap + k0 + 4);
        av[2] = *(const float4*)(Ap + k0 + 8);
        av[3] = *(const float4*)(Ap + k0 + 12);
        bvh = *(const uint2*)(Bph + k0);
        bvl = *(const uint2*)(Bpl + k0);
    };
    auto sts = [&](int s) {
        char* base = smg + s * STG3;
        const float* af = (const float*)av;
        uint32_t hp[8], lp[8];
#pragma unroll
        for (int j = 0; j < 8; j++) {
            float x0 = af[2 * j], x1 = af[2 * j + 1];
            __nv_bfloat16 h0 = __float2bfloat16(x0), h1 = __float2bfloat16(x1);
            hp[j] = ((uint32_t)__bfloat16_as_ushort(h1) << 16) |
                    __bfloat16_as_ushort(h0);
            lp[j] = pack_bf2(x0 - __bfloat162float(h0), x1 - __bfloat162float(h1));
        }
        *(uint4*)(base + a_sts)           = make_uint4(hp[0], hp[1], hp[2], hp[3]);
        *(uint4*)(base + a_sts + 16)      = make_uint4(hp[4], hp[5], hp[6], hp[7]);
        *(uint4*)(base + AL_OFF + a_sts)      = make_uint4(lp[0], lp[1], lp[2], lp[3]);
        *(uint4*)(base + AL_OFF + a_sts + 16) = make_uint4(lp[4], lp[5], lp[6], lp[7]);
        *(uint2*)(base + BH_OFF + b_sts) = bvh;
        *(uint2*)(base + BL_OFF + b_sts) = bvl;
    };

    float acc[2][2][4] = {};
    const int nch = K >> 5;

    ldg(0);
    sts(0);
    __syncthreads();

    for (int c = 0; c < nch; ++c) {
        const int buf = c & 1;
        if (c + 1 < nch) ldg((c + 1) << 5);

        const uint32_t ab = sb + buf * STG3 + a_lds;
        const uint32_t bb = sb + buf * STG3 + BH_OFF + b_lds;
#pragma unroll
        for (int kk = 0; kk < 2; kk++) {
            const uint32_t ko = kk * 32;
            uint32_t ah[2][4], al[2][4], bh[4], bl[4];
#pragma unroll
            for (int mr = 0; mr < 2; mr++) {
                LDSM4(ah[mr][0], ah[mr][1], ah[mr][2], ah[mr][3],
                      ab + mr * 1280 + ko);
                LDSM4(al[mr][0], al[mr][1], al[mr][2], al[mr][3],
                      ab + AL_OFF + mr * 1280 + ko);
            }
            LDSM4(bh[0], bh[1], bh[2], bh[3], bb + ko);
            LDSM4(bl[0], bl[1], bl[2], bl[3], bb + 2560 + ko);
#pragma unroll
            for (int mr = 0; mr < 2; mr++) {
                float* c0 = acc[mr][0];
                float* c1 = acc[mr][1];
                mma_bf16(c0, ah[mr][0], ah[mr][1], ah[mr][2], ah[mr][3], bh[0], bh[2]);
                mma_bf16(c0, ah[mr][0], ah[mr][1], ah[mr][2], ah[mr][3], bl[0], bl[2]);
                mma_bf16(c0, al[mr][0], al[mr][1], al[mr][2], al[mr][3], bh[0], bh[2]);
                mma_bf16(c1, ah[mr][0], ah[mr][1], ah[mr][2], ah[mr][3], bh[1], bh[3]);
                mma_bf16(c1, ah[mr][0], ah[mr][1], ah[mr][2], ah[mr][3], bl[1], bl[3]);
                mma_bf16(c1, al[mr][0], al[mr][1], al[mr][2], al[mr][3], bh[1], bh[3]);
            }
        }
        if (c + 1 < nch) sts((c + 1) & 1);
        __syncthreads();
    }

    const int gid = lane >> 2, tig = lane & 3;
#pragma unroll
    for (int mr = 0; mr < 2; mr++) {
#pragma unroll
        for (int nc = 0; nc < 2; nc++) {
            int m = m0 + wm * 32 + mr * 16 + gid;
            int n = n0 + wn * 16 + nc * 8 + tig * 2;
            float b0 = 0.f, b1 = 0.f;
            if (bias) {
                b0 = bias[(size_t)z * bias_bs + n];
                b1 = bias[(size_t)z * bias_bs + n + 1];
            }
            float2 o0, o1;
            o0.x = fmaf(acc[mr][nc][0], alpha, b0);
            o0.y = fmaf(acc[mr][nc][1], alpha, b1);
            o1.x = fmaf(acc[mr][nc][2], alpha, b0);
            o1.y = fmaf(acc[mr][nc][3], alpha, b1);
            *(float2*)&C[(size_t)z * c_bs + (size_t)m * ldc + n] = o0;
            *(float2*)&C[(size_t)z * c_bs + (size_t)(m + 8) * ldc + n] = o1;
        }
    }
}

// ---------------------------------------------------------------------------
// Merged prep (unchanged)
// ---------------------------------------------------------------------------
__device__ __forceinline__ void split4(const float* __restrict__ s, int i,
                                       __nv_bfloat16* __restrict__ h,
                                       __nv_bfloat16* __restrict__ l)
{
    float4 v = *(const float4*)(s);
    __nv_bfloat16 h0 = __float2bfloat16(v.x), h1 = __float2bfloat16(v.y);
    __nv_bfloat16 h2 = __float2bfloat16(v.z), h3 = __float2bfloat16(v.w);
    uint2 hw, lw;
    hw.x = ((uint32_t)__bfloat16_as_ushort(h1) << 16) | __bfloat16_as_ushort(h0);
    hw.y = ((uint32_t)__bfloat16_as_ushort(h3) << 16) | __bfloat16_as_ushort(h2);
    lw.x = pack_bf2(v.x - __bfloat162float(h0), v.y - __bfloat162float(h1));
    lw.y = pack_bf2(v.z - __bfloat162float(h2), v.w - __bfloat162float(h3));
    *(uint2*)(h + i) = hw;
    *(uint2*)(l + i) = lw;
}

__global__ __launch_bounds__(256) void prep_kernel(
    const float* __restrict__ Wg, const float* __restrict__ Wb,
    const float* __restrict__ Wl, const float* __restrict__ Wq,
    const float* __restrict__ Wo, const float* __restrict__ Wv,
    const float* __restrict__ bg, const float* __restrict__ bb,
    __nv_bfloat16* __restrict__ wgb_h, __nv_bfloat16* __restrict__ wgb_l,
    __nv_bfloat16* __restrict__ wl_h, __nv_bfloat16* __restrict__ wl_l,
    __nv_bfloat16* __restrict__ wq_h, __nv_bfloat16* __restrict__ wq_l,
    __nv_bfloat16* __restrict__ wo_h, __nv_bfloat16* __restrict__ wo_l,
    __nv_bfloat16* __restrict__ wv_h, __nv_bfloat16* __restrict__ wv_l,
    float* __restrict__ bgb)
{
    const int blk = blockIdx.x, t4 = threadIdx.x * 4;
    if (blk < 512) {
        int i = blk * 1024 + t4;
        const float* s = (i < Fd * Zd) ? (Wg + i) : (Wb + (i - Fd * Zd));
        split4(s, i, wgb_h, wgb_l);
    } else if (blk < 1536) {
        int i = (blk - 512) * 1024 + t4;
        split4(Wl + i, i, wl_h, wl_l);
    } else if (blk < 2560) {
        int i = (blk - 1536) * 1024 + t4;
        split4(Wq + i, i, wq_h, wq_l);
    } else if (blk < 3584) {
        int i = (blk - 2560) * 1024 + t4;
        split4(Wo + i, i, wo_h, wo_l);
    } else if (blk < 4352) {
        int i = (blk - 3584) * 1024 + t4;
        split4(Wv + i, i, wv_h, wv_l);
    } else {
        int i = (blk - 4352) * 1024 + t4;
        const float* s = (i < Fd) ? (bg + i) : (bb + (i - Fd));
        *(float4*)(bgb + i) = *(const float4*)s;
    }
}

__global__ __launch_bounds__(256) void splitT_wk(
    const float* __restrict__ w, __nv_bfloat16* __restrict__ h,
    __nv_bfloat16* __restrict__ l)
{
    int idx = blockIdx.x * 256 + threadIdx.x;
    int d = idx & 127;
    int c = (idx >> 7) % Td;
    int hh = idx / (128 * Td);
    float v = w[((size_t)hh * 128 + d) * Td + c];
    __nv_bfloat16 hi = __float2bfloat16(v);
    h[idx] = hi;
    l[idx] = __float2bfloat16(v - __bfloat162float(hi));
}

// ---------------------------------------------------------------------------
// LayerNorm + FiLM (unchanged)
// ---------------------------------------------------------------------------
__global__ __launch_bounds__(256) void ln_film_kernel(
    const float* __restrict__ h1, const float* __restrict__ g,
    const float* __restrict__ bb, const float* __restrict__ gb,
    float* __restrict__ out)
{
    int r = blockIdx.x, tid = threadIdx.x;
    __shared__ float red1[8], red2[8], mv[2];
    const float* row = h1 + (size_t)r * Fd;
    float v[4], s = 0.f, s2 = 0.f;
#pragma unroll
    for (int i = 0; i < 4; i++) {
        v[i] = row[tid + i * 256];
        s += v[i]; s2 += v[i] * v[i];
    }
#pragma unroll
    for (int o = 16; o; o >>= 1) {
        s += __shfl_xor_sync(~0u, s, o);
        s2 += __shfl_xor_sync(~0u, s2, o);
    }
    if ((tid & 31) == 0) { red1[tid >> 5] = s; red2[tid >> 5] = s2; }
    __syncthreads();
    if (tid == 0) {
        float a = 0.f, b2 = 0.f;
        for (int w = 0; w < 8; w++) { a += red1[w]; b2 += red2[w]; }
        mv[0] = a * (1.f / Fd); mv[1] = b2 * (1.f / Fd);
    }
    __syncthreads();
    float mu = mv[0], var = mv[1] - mu * mu;
    float rstd = rsqrtf(var + 1e-5f);
#pragma unroll
    for (int i = 0; i < 4; i++) {
        int f = tid + i * 256;
        float y = (v[i] - mu) * rstd * g[f] + bb[f];
        float gamma = gb[(size_t)r * 2048 + f];
        float beta  = gb[(size_t)r * 2048 + 1024 + f];
        out[(size_t)r * Fd + f] = y * (1.f + gamma) + beta;
    }
}

__global__ __launch_bounds__(256) void ln_add_gelu_kernel(
    const float* __restrict__ ao, const float* __restrict__ g,
    const float* __restrict__ bb, const float* __restrict__ res,
    float* __restrict__ y)
{
    int r = blockIdx.x, tid = threadIdx.x;
    __shared__ float red1[8], red2[8], mv[2];
    const float* row = ao + (size_t)r * Fd;
    float v[4], s = 0.f, s2 = 0.f;
#pragma unroll
    for (int i = 0; i < 4; i++) {
        v[i] = row[tid + i * 256];
        s += v[i]; s2 += v[i] * v[i];
    }
#pragma unroll
    for (int o = 16; o; o >>= 1) {
        s += __shfl_xor_sync(~0u, s, o);
        s2 += __shfl_xor_sync(~0u, s2, o);
    }
    if ((tid & 31) == 0) { red1[tid >> 5] = s; red2[tid >> 5] = s2; }
    __syncthreads();
    if (tid == 0) {
        float a = 0.f, b2 = 0.f;
        for (int w = 0; w < 8; w++) { a += red1[w]; b2 += red2[w]; }
        mv[0] = a * (1.f / Fd); mv[1] = b2 * (1.f / Fd);
    }
    __syncthreads();
    float mu = mv[0], var = mv[1] - mu * mu;
    float rstd = rsqrtf(var + 1e-5f);
#pragma unroll
    for (int i = 0; i < 4; i++) {
        int f = tid + i * 256;
        float t = res[(size_t)r * Fd + f] + ((v[i] - mu) * rstd * g[f] + bb[f]);
        y[(size_t)r * Fd + f] = t * normcdff(t);
    }
}

// ---------------------------------------------------------------------------
// Fused attention v7: score pass via mma.sync (16t x 8h x 768c GEMM,
// k-split across 8 warps, q-fragments chunk-invariant in registers),
// online softmax on warp 0 (shuffle-parallel over t), u-pass FMA2 c-split.
// Text loaded once, split to bf16 hi/lo tiles (Markidis 3-pass numerics).
// ---------------------------------------------------------------------------
#define TPITCH 776                         // bf16 pitch per t-row (conflict-free LDSM)
#define TILE_BYTES (16 * TPITCH * 2)       // 24832
#define PS_OFF (2 * TILE_BYTES)            // partial scores [8][16][8] f32
#define PSM_OFF (PS_OFF + 4096)            // p [16][8] f32
#define RS_OFF (PSM_OFF + 512)             // rs [8]
#define IL_OFF (RS_OFF + 32)               // 1/l [8]
#define ATTN_SMEM (IL_OFF + 32)

__global__ __launch_bounds__(256) void attn_kernel(
    const float* __restrict__ text, const int* __restrict__ att,
    const float* __restrict__ qt, float* __restrict__ u)
{
    extern __shared__ char sma[];
    __nv_bfloat16* th = (__nv_bfloat16*)sma;
    __nv_bfloat16* tl = th + 16 * TPITCH;
    float* ps    = (float*)(sma + PS_OFF);
    float* p_sm  = (float*)(sma + PSM_OFF);
    float* rs_sm = (float*)(sma + RS_OFF);
    float* il_sm = (float*)(sma + IL_OFF);
    __shared__ int s_att[128];

    const int b = blockIdx.x, tid = threadIdx.x;
    const int w = tid >> 5, lane = tid & 31;
    const int cw = w * 96;

    // --- q-fragments (B of m16n8k16), chunk-invariant, built from gmem ---
    // frag layout: lane t: n(head) = t>>2; reg r: k_local = (t&3)*2 + r*8
    uint32_t qh[6][2], ql[6][2];
    {
        const float* qb = qt + (size_t)b * (Hn * Td) + (lane >> 2) * Td;
#pragma unroll
        for (int s = 0; s < 6; s++)
#pragma unroll
            for (int r = 0; r < 2; r++) {
                int c0 = cw + s * 16 + (lane & 3) * 2 + r * 8;
                float2 v = *(const float2*)(qb + c0);
                __nv_bfloat16 h0 = __float2bfloat16(v.x);
                __nv_bfloat16 h1 = __float2bfloat16(v.y);
                qh[s][r] = ((uint32_t)__bfloat16_as_ushort(h1) << 16) |
                           __bfloat16_as_ushort(h0);
                ql[s][r] = pack_bf2(v.x - __bfloat162float(h0),
                                    v.y - __bfloat162float(h1));
            }
    }

    unsigned long long u2[4][3] = {};   // u accumulators, packed head pairs
    float m_run4[4], l_run4[4];         // softmax state (warp 0 only)
#pragma unroll
    for (int q = 0; q < 4; q++) { m_run4[q] = -INFINITY; l_run4[q] = 0.f; }

    for (int i = tid; i < 128; i += 256) s_att[i] = att[b * 128 + i];

    const float* tb = text + (size_t)b * Tsz * Td;
    const uint32_t th_base = smem_u32(th);
    const uint32_t a_lds = th_base +
        ((lane & 15) * TPITCH + cw + (lane >> 4) * 8) * 2;

    for (int tc = 0; tc < 8; tc++) {
        __syncthreads();
        // load text chunk, split to bf16 hi/lo tiles
        for (int i = tid; i < 3072; i += 256) {
            float4 v = *(const float4*)(tb + tc * 12288 + i * 4);
            int t = (i * 4) / 768, c = (i * 4) % 768;
            int addr = t * TPITCH + c;
            __nv_bfloat16 h0 = __float2bfloat16(v.x), h1 = __float2bfloat16(v.y);
            __nv_bfloat16 h2 = __float2bfloat16(v.z), h3 = __float2bfloat16(v.w);
            uint2 hw, lw;
            hw.x = ((uint32_t)__bfloat16_as_ushort(h1) << 16) |
                   __bfloat16_as_ushort(h0);
            hw.y = ((uint32_t)__bfloat16_as_ushort(h3) << 16) |
                   __bfloat16_as_ushort(h2);
            lw.x = pack_bf2(v.x - __bfloat162float(h0), v.y - __bfloat162float(h1));
            lw.y = pack_bf2(v.z - __bfloat162float(h2), v.w - __bfloat162float(h3));
            *(uint2*)&th[addr] = hw;
            *(uint2*)&tl[addr] = lw;
        }
        __syncthreads();

        // --- score mma: this warp's 96-channel k-slice ---
        float acc[4] = {0.f, 0.f, 0.f, 0.f};
#pragma unroll
        for (int s = 0; s < 6; s++) {
            uint32_t Ah[4], Al[4];
            LDSM4(Ah[0], Ah[1], Ah[2], Ah[3], a_lds + s * 32);
            LDSM4(Al[0], Al[1], Al[2], Al[3], a_lds + TILE_BYTES + s * 32);
            mma_bf16(acc, Ah[0], Ah[1], Ah[2], Ah[3], qh[s][0], qh[s][1]);
            mma_bf16(acc, Ah[0], Ah[1], Ah[2], Ah[3], ql[s][0], ql[s][1]);
            mma_bf16(acc, Al[0], Al[1], Al[2], Al[3], qh[s][0], qh[s][1]);
        }
        // partial scores: acc rows t = (lane>>2), (lane>>2)+8; cols h = (lane&3)*2,+1
        *(float2*)&ps[w * 128 + (lane >> 2) * 8 + (lane & 3) * 2] =
            make_float2(acc[0], acc[1]);
        *(float2*)&ps[w * 128 + ((lane >> 2) + 8) * 8 + (lane & 3) * 2] =
            make_float2(acc[2], acc[3]);
        __syncthreads();

        // --- online softmax on warp 0: lane = (t = lane>>1, hq = (lane&1)*4) ---
        if (w == 0) {
            const int t = lane >> 1, hq = (lane & 1) * 4;
            float s4[4] = {0.f, 0.f, 0.f, 0.f};
#pragma unroll
            for (int ww = 0; ww < 8; ww++) {
                float4 pv = *(float4*)&ps[ww * 128 + t * 8 + hq];
                s4[0] += pv.x; s4[1] += pv.y; s4[2] += pv.z; s4[3] += pv.w;
            }
            const bool ok = s_att[tc * 16 + t] != 0;
            float p4[4], rs4[4];
#pragma unroll
            for (int q = 0; q < 4; q++) {
                float sc = ok ? s4[q] : -INFINITY;
                float mx = sc;
#pragma unroll
                for (int off = 2; off < 32; off <<= 1)
                    mx = fmaxf(mx, __shfl_xor_sync(~0u, mx, off));
                mx = fmaxf(mx, m_run4[q]);
                float p = (sc == -INFINITY) ? 0.f : expf(sc - mx);
                float rs = (mx == -INFINITY) ? 1.f : expf(m_run4[q] - mx);
                float psum = p;
#pragma unroll
                for (int off = 2; off < 32; off <<= 1)
                    psum += __shfl_xor_sync(~0u, psum, off);
                l_run4[q] = l_run4[q] * rs + psum;
                m_run4[q] = mx;
                p4[q] = p; rs4[q] = rs;
            }
            *(float4*)&p_sm[t * 8 + hq] = make_float4(p4[0], p4[1], p4[2], p4[3]);
            if (t == 0)
                *(float4*)&rs_sm[hq] = make_float4(rs4[0], rs4[1], rs4[2], rs4[3]);
        }
        __syncthreads();

        // --- u pass: c-split, FMA2 over head pairs ---
        unsigned long long rs2[4];
#pragma unroll
        for (int hp = 0; hp < 4; hp++) {
            float2 rv = *(const float2*)&rs_sm[2 * hp];
            PACK2(rs2[hp], rv.x, rv.y);
        }
#pragma unroll
        for (int hp = 0; hp < 4; hp++)
#pragma unroll
            for (int j = 0; j < 3; j++) MUL2(u2[hp][j], rs2[hp]);

#pragma unroll
        for (int t = 0; t < 16; t++) {
            unsigned long long xx[3];
#pragma unroll
            for (int j = 0; j < 3; j++) {
                int o = t * TPITCH + cw + lane + 32 * j;
                float x = __bfloat162float(th[o]) + __bfloat162float(tl[o]);
                PACK2(xx[j], x, x);
            }
            unsigned long long p2[4];
#pragma unroll
            for (int hp = 0; hp < 4; hp++) {
                float2 pv = *(const float2*)&p_sm[t * 8 + 2 * hp];
                PACK2(p2[hp], pv.x, pv.y);
            }
#pragma unroll
            for (int hp = 0; hp < 4; hp++) {
                FMA2(u2[hp][0], p2[hp], xx[0]);
                FMA2(u2[hp][1], p2[hp], xx[1]);
                FMA2(u2[hp][2], p2[hp], xx[2]);
            }
        }
    }

    if (w == 0 && (lane >> 1) == 0) {
        const int hq = (lane & 1) * 4;
#pragma unroll
        for (int q = 0; q < 4; q++) il_sm[hq + q] = 1.f / l_run4[q];
    }
    __syncthreads();

    float* ub = u + (size_t)b * (Hn * Td);
#pragma unroll
    for (int hp = 0; hp < 4; hp++) {
        float il0 = il_sm[2 * hp], il1 = il_sm[2 * hp + 1];
#pragma unroll
        for (int j = 0; j < 3; j++) {
            float lo, hi;
            UNPACK2(lo, hi, u2[hp][j]);
            ub[(2 * hp) * Td + cw + lane + 32 * j]     = lo * il0;
            ub[(2 * hp + 1) * Td + cw + lane + 32 * j] = hi * il1;
        }
    }
}

// ---------------------------------------------------------------------------
extern "C" void kernel_launch(void* const* d_in, const int* in_sizes, int n_in,
                              void* d_out, int out_size)
{
    const float* x    = (const float*)d_in[0];
    const float* z    = (const float*)d_in[1];
    const float* text = (const float*)d_in[2];
    const int*   att  = (const int*)d_in[3];
    const float* Wg = (const float*)d_in[4];  const float* bg = (const float*)d_in[5];
    const float* Wb = (const float*)d_in[6];  const float* bb = (const float*)d_in[7];
    const float* Wl = (const float*)d_in[8];  const float* bl = (const float*)d_in[9];
    const float* g1 = (const float*)d_in[10]; const float* b1 = (const float*)d_in[11];
    const float* Wq = (const float*)d_in[12]; const float* bq = (const float*)d_in[13];
    const float* Wk = (const float*)d_in[14]; /* bk softmax-invariant: dropped */
    const float* Wv = (const float*)d_in[16]; const float* bv = (const float*)d_in[17];
    const float* Wo = (const float*)d_in[18]; const float* bo = (const float*)d_in[19];
    const float* g2 = (const float*)d_in[20]; const float* b2 = (const float*)d_in[21];
    float* y = (float*)d_out;

    float *p_gb, *p_h1, *p_out, *p_q, *p_qt, *p_u, *p_ctx, *p_ao, *p_bgb;
    cudaGetSymbolAddress((void**)&p_gb,  g_gb);
    cudaGetSymbolAddress((void**)&p_h1,  g_h1);
    cudaGetSymbolAddress((void**)&p_out, g_out);
    cudaGetSymbolAddress((void**)&p_q,   g_q);
    cudaGetSymbolAddress((void**)&p_qt,  g_qt);
    cudaGetSymbolAddress((void**)&p_u,   g_u);
    cudaGetSymbolAddress((void**)&p_ctx, g_ctx);
    cudaGetSymbolAddress((void**)&p_ao,  g_ao);
    cudaGetSymbolAddress((void**)&p_bgb, g_bgb);

    __nv_bfloat16 *wgb_h, *wgb_l, *wl_h, *wl_l, *wq_h, *wq_l;
    __nv_bfloat16 *wo_h, *wo_l, *wv_h, *wv_l, *wk_h, *wk_l;
    cudaGetSymbolAddress((void**)&wgb_h, g_Wgb_h);
    cudaGetSymbolAddress((void**)&wgb_l, g_Wgb_l);
    cudaGetSymbolAddress((void**)&wl_h, g_Wl_h); cudaGetSymbolAddress((void**)&wl_l, g_Wl_l);
    cudaGetSymbolAddress((void**)&wq_h, g_Wq_h); cudaGetSymbolAddress((void**)&wq_l, g_Wq_l);
    cudaGetSymbolAddress((void**)&wo_h, g_Wo_h); cudaGetSymbolAddress((void**)&wo_l, g_Wo_l);
    cudaGetSymbolAddress((void**)&wv_h, g_Wv_h); cudaGetSymbolAddress((void**)&wv_l, g_Wv_l);
    cudaGetSymbolAddress((void**)&wk_h, g_WkT_h); cudaGetSymbolAddress((void**)&wk_l, g_WkT_l);

    cudaFuncSetAttribute(bgemm3, cudaFuncAttributeMaxDynamicSharedMemorySize,
                         GEMM_SMEM);
    cudaFuncSetAttribute(attn_kernel, cudaFuncAttributeMaxDynamicSharedMemorySize,
                         ATTN_SMEM);

    dim3 blk(256);

    prep_kernel<<<4354, blk>>>(Wg, Wb, Wl, Wq, Wo, Wv, bg, bb,
                               wgb_h, wgb_l, wl_h, wl_l, wq_h, wq_l,
                               wo_h, wo_l, wv_h, wv_l, p_bgb);
    splitT_wk<<<(Hn * Td * Dh) / 256, blk>>>(Wk, wk_h, wk_l);

    // gamma||beta = z @ [Wg;Wb]^T + [bg;bb]
    bgemm3<<<dim3(64, 8, 1), blk, GEMM_SMEM>>>(z, Zd, 0, wgb_h, wgb_l, Zd, 0,
                                               p_bgb, 0, p_gb, 2 * Fd, 0, Zd, 1.f);
    // h1 = x @ Wl^T + bl
    bgemm3<<<dim3(32, 8, 1), blk, GEMM_SMEM>>>(x, Fd, 0, wl_h, wl_l, Fd, 0, bl, 0,
                                               p_h1, Fd, 0, Fd, 1.f);
    ln_film_kernel<<<1024, blk>>>(p_h1, g1, b1, p_gb, p_out);
    // q = out @ Wq^T + bq
    bgemm3<<<dim3(32, 8, 1), blk, GEMM_SMEM>>>(p_out, Fd, 0, wq_h, wq_l, Fd, 0,
                                               bq, 0, p_q, Fd, 0, Fd, 1.f);
    // qt = (1/sqrt(d)) q_h @ WkT_h  (batched over heads)
    bgemm3<<<dim3(24, 8, 8), blk, GEMM_SMEM>>>(p_q, Fd, Dh, wk_h, wk_l, Dh,
                                               Td * Dh, nullptr, 0,
                                               p_qt, Hn * Td, Td, Dh,
                                               0.08838834764831845f);
    // fused attention (mma score pass)
    attn_kernel<<<1024, blk, ATTN_SMEM>>>(text, att, p_qt, p_u);
    // ctx = u @ Wv^T + bv
    bgemm3<<<dim3(4, 8, 8), blk, GEMM_SMEM>>>(p_u, Hn * Td, Td, wv_h, wv_l, Td,
                                              Dh * Td, bv, Dh,
                                              p_ctx, Fd, Dh, Td, 1.f);
    // attn_out = ctx @ Wo^T + bo
    bgemm3<<<dim3(32, 8, 1), blk, GEMM_SMEM>>>(p_ctx, Fd, 0, wo_h, wo_l, Fd, 0,
                                               bo, 0, p_ao, Fd, 0, Fd, 1.f);
    ln_add_gelu_kernel<<<1024, blk>>>(p_ao, g2, b2, p_out, y);
}